// round 8
// baseline (speedup 1.0000x reference)
#include <cuda_runtime.h>
#include <math.h>
#include <stdint.h>
#include <stddef.h>

#define TSTEPS 256
#define HID    1024
#define NB     256
#define KC     2048
#define NG     4096
#define SOFF   ((size_t)NB * TSTEPS * HID)

// ---------------- static device scratch ----------------
__device__ __align__(256) float d_Wt[(size_t)NG * KC];    // reordered [n'=4d+g][k]; k<1024: W_c (tf32), k>=1024: W_hh (tf32)
__device__ __align__(256) float d_Ac0[(size_t)NB * HID];  // c-part A ping-pong (tf32-rounded)
__device__ __align__(256) float d_Ac1[(size_t)NB * HID];
__device__ __align__(256) float d_Ah0[(size_t)NB * HID];  // h-part A ping-pong (tf32-rounded)
__device__ __align__(256) float d_Ah1[(size_t)NB * HID];
__device__ __align__(256) float d_Wf[(size_t)HID * HID];  // tf32-rounded W_fc [o][h]
__device__ __align__(256) float d_P[2 * 64 * 16384];      // split-K partials: [kz][tile][128*128]
__device__ int   d_cnt[64];                               // per-tile rendezvous counters (zero at rest)
__device__ float d_b0[NG];                                // reordered b_ih+b_hh          (t = 0)
__device__ float d_bF[NG];                                // reordered + W_ih@b_fc folded (t >= 1)

__device__ __forceinline__ float sigf(float x) { return 1.0f / (1.0f + expf(-x)); }
__device__ __forceinline__ float tf32r(float x) {
    uint32_t u; asm("cvt.rna.tf32.f32 %0, %1;" : "=r"(u) : "f"(x));
    return __uint_as_float(u);
}
__device__ __forceinline__ uint32_t smem_u32(const void* p) {
    uint32_t a;
    asm("{ .reg .u64 t; cvta.to.shared.u64 t, %1; cvt.u32.u64 %0, t; }" : "=r"(a) : "l"(p));
    return a;
}

#define CPA(dst, src) asm volatile("cp.async.cg.shared.global [%0], [%1], 16;" :: "r"(dst), "l"(src))
#define CPC()         asm volatile("cp.async.commit_group;" ::: "memory")
#define CPW(n)        asm volatile("cp.async.wait_group %0;" :: "n"(n) : "memory")

#define MMA8(d, a, b) asm volatile( \
    "mma.sync.aligned.m16n8k8.row.col.f32.tf32.tf32.f32 " \
    "{%0,%1,%2,%3}, {%4,%5,%6,%7}, {%8,%9}, {%0,%1,%2,%3};" \
    : "+f"((d)[0]), "+f"((d)[1]), "+f"((d)[2]), "+f"((d)[3]) \
    : "r"((a)[0]), "r"((a)[1]), "r"((a)[2]), "r"((a)[3]), "r"((b)[0]), "r"((b)[1]))

// ---------------- GEMM tiling: CTA 128x128, 4 warps (warp tile 64x64), BK=32, 3 stages ----------------
#define BM     128
#define BN     128
#define BK     32
#define STAGES 3
#define ASTR   36
#define ASZ    (BM * ASTR)            // 4608 floats
#define BSZ    (BN * ASTR)            // 4608 floats
#define STG_F  (ASZ + BSZ)            // 9216 floats / stage
#define SMEM_BYTES (STAGES * STG_F * 4)   // 110592 B; Cs tile (64KB) reuses this

// ================= tf32 mma.sync GEMM =================
// MODE 0: split-K gates GEMM + fused rendezvous combine + LSTM cell epilogue
// MODE 1: plain GEMM + bias (final outputs)
template<int MODE>
__global__ void __launch_bounds__(128) gemm_k(
    const float* __restrict__ Ac, const float* __restrict__ Ah, long long lda,
    const float* __restrict__ Bg, long long ldb,
    const float* __restrict__ pb,
    const float* __restrict__ cvec,
    float* __restrict__ pout, long long ldo,
    float* __restrict__ pAc, float* __restrict__ pAh,
    int t, int ktot)
{
    extern __shared__ __align__(16) float sm[];
    const int tid = threadIdx.x;
    const int n0 = blockIdx.x * BN;
    const int m0 = blockIdx.y * BM;
    const int kz = blockIdx.z;
    const int w = tid >> 5, lane = tid & 31;
    const int wm = w & 1, wn = w >> 1;          // 2 x 2 warp grid, warp tile 64x64
    const int gid = lane >> 2, tig = lane & 3;

    const float* Ag = (MODE == 0) ? (kz ? Ah : Ac) : Ac;
    const float* Bb = Bg + ((MODE == 0) ? kz * 1024 : 0);

    const float* Atile = Ag + (size_t)m0 * lda;
    const float* Btile = Bb + (size_t)n0 * ldb;
    const uint32_t sbase = smem_u32(sm);

    float acc[4][8][4];
    #pragma unroll
    for (int i = 0; i < 4; i++)
        #pragma unroll
        for (int j = 0; j < 8; j++)
            #pragma unroll
            for (int q = 0; q < 4; q++) acc[i][j][q] = 0.f;

    const int KT = ktot / BK;

    auto load_stage = [&](int stage, int kt) {
        uint32_t sa = sbase + (uint32_t)(stage * STG_F) * 4u;
        uint32_t sb = sa + (uint32_t)ASZ * 4u;
        #pragma unroll
        for (int i = 0; i < 8; i++) {
            int idx = tid + i * 128;            // 0..1023
            int r = idx >> 3, c = (idx & 7) * 4;
            CPA(sa + (uint32_t)(r * ASTR + c) * 4u, Atile + (size_t)r * lda + kt + c);
        }
        #pragma unroll
        for (int i = 0; i < 8; i++) {
            int idx = tid + i * 128;
            int r = idx >> 3, c = (idx & 7) * 4;
            CPA(sb + (uint32_t)(r * ASTR + c) * 4u, Btile + (size_t)r * ldb + kt + c);
        }
        CPC();
    };

    load_stage(0, 0);
    load_stage(1, BK);

    for (int kt = 0; kt < KT; kt++) {
        CPW(STAGES - 2);
        __syncthreads();
        int kn = kt + STAGES - 1;
        if (kn < KT) load_stage(kn % STAGES, kn * BK); else CPC();

        const float* sA = sm + (size_t)(kt % STAGES) * STG_F;
        const float* sB = sA + ASZ;
        #pragma unroll
        for (int ks = 0; ks < 4; ks++) {
            int k0 = ks * 8;
            uint32_t a[4][4], b[8][2];
            #pragma unroll
            for (int mt = 0; mt < 4; mt++) {
                int mr = wm * 64 + mt * 16 + gid;
                a[mt][0] = __float_as_uint(sA[(mr)     * ASTR + k0 + tig]);
                a[mt][1] = __float_as_uint(sA[(mr + 8) * ASTR + k0 + tig]);
                a[mt][2] = __float_as_uint(sA[(mr)     * ASTR + k0 + tig + 4]);
                a[mt][3] = __float_as_uint(sA[(mr + 8) * ASTR + k0 + tig + 4]);
            }
            #pragma unroll
            for (int nt = 0; nt < 8; nt++) {
                int nc = wn * 64 + nt * 8 + gid;
                b[nt][0] = __float_as_uint(sB[nc * ASTR + k0 + tig]);
                b[nt][1] = __float_as_uint(sB[nc * ASTR + k0 + tig + 4]);
            }
            #pragma unroll
            for (int mt = 0; mt < 4; mt++)
                #pragma unroll
                for (int nt = 0; nt < 8; nt++)
                    MMA8(acc[mt][nt], a[mt], b[nt]);
        }
        __syncthreads();
    }

    // ---- stash C tile to smem ----
    float* Cs = sm;
    #pragma unroll
    for (int mt = 0; mt < 4; mt++) {
        int row = wm * 64 + mt * 16 + gid;
        #pragma unroll
        for (int nt = 0; nt < 8; nt++) {
            int col = wn * 64 + nt * 8 + 2 * tig;
            *(float2*)&Cs[(row)     * BN + col] = make_float2(acc[mt][nt][0], acc[mt][nt][1]);
            *(float2*)&Cs[(row + 8) * BN + col] = make_float2(acc[mt][nt][2], acc[mt][nt][3]);
        }
    }
    __syncthreads();

    if (MODE == 1) {
        #pragma unroll
        for (int i = 0; i < 32; i++) {
            int e = tid + i * 128;                  // 0..4095 float4 slots
            int r = e >> 5, c4 = (e & 31) * 4;
            float4 v = *(float4*)&Cs[r * BN + c4];
            float4 bz = *(const float4*)&pb[n0 + c4];
            v = make_float4(v.x + bz.x, v.y + bz.y, v.z + bz.z, v.w + bz.w);
            *(float4*)&pout[(size_t)(m0 + r) * ldo + n0 + c4] = v;
        }
        return;
    }

    // ================= MODE 0: split-K rendezvous + fused LSTM cell =================
    const int tile = blockIdx.y * gridDim.x + blockIdx.x;      // 0..63
    float* slot = d_P + ((size_t)kz * 64 + tile) * 16384;

    // publish my partial (linear [r*BN + c])
    #pragma unroll
    for (int i = 0; i < 32; i++) {
        int e = tid + i * 128;
        *(float4*)&slot[4 * e] = *(float4*)&Cs[4 * e];
    }
    __syncthreads();

    __shared__ int amSecond;
    if (tid == 0) {
        __threadfence();
        int old = atomicAdd(&d_cnt[tile], 1);
        amSecond = (old == 1);
    }
    __syncthreads();
    if (!amSecond) return;
    __threadfence();

    const float* other = d_P + ((size_t)(1 - kz) * 64 + tile) * 16384;

    #pragma unroll
    for (int i = 0; i < 32; i++) {
        int e = tid + i * 128;                  // 0..4095 cells
        int bl = e >> 5, dl = e & 31;
        float4 me = *(float4*)&Cs[bl * BN + 4 * dl];
        float4 ot = *(const float4*)&other[bl * BN + 4 * dl];
        float4 bz = *(const float4*)&pb[n0 + 4 * dl];
        float ig = me.x + ot.x + bz.x;
        float fg = me.y + ot.y + bz.y;
        float gg = me.z + ot.z + bz.z;
        float og = me.w + ot.w + bz.w;
        int bg = m0 + bl;
        int d  = (n0 >> 2) + dl;
        float cp = (t == 0) ? cvec[(size_t)bg * HID + d]
                            : pout[SOFF + (size_t)bg * (TSTEPS * HID) + (size_t)(t - 1) * HID + d];
        float cn = sigf(fg) * cp + sigf(ig) * tanhf(gg);
        float hn = sigf(og) * tanhf(cn);
        size_t ro = (size_t)bg * (TSTEPS * HID) + (size_t)t * HID + d;
        pout[ro]        = hn;
        pout[SOFF + ro] = cn;
        pAc[(size_t)bg * HID + d] = tf32r(cn);
        pAh[(size_t)bg * HID + d] = tf32r(hn);
    }
    __syncthreads();
    if (tid == 0) d_cnt[tile] = 0;              // reset for next step (next launch)
}

// ================= prep kernels =================
// W_c = W_ih @ W_fc (exact fp32 SIMT), stored reordered + tf32-rounded into d_Wt[:, 0:1024]
__global__ void prep_wc(const float* __restrict__ Wih, const float* __restrict__ Wfc) {
    __shared__ float As[16][65];
    __shared__ float Bs[16][64];
    int n0 = blockIdx.x * 64;          // output k (0..1023)
    int m0 = blockIdx.y * 64;          // row of W_ih (gate-major n, 0..4095)
    int tid = threadIdx.x;
    int tx = tid & 15, ty = tid >> 4;
    int lmA = tid >> 2, lkA = (tid & 3) * 4;
    int lkB = tid >> 4, lnB = (tid & 15) * 4;
    float acc[4][4] = {};
    for (int kt = 0; kt < HID; kt += 16) {
        float4 a = *(const float4*)&Wih[(size_t)(m0 + lmA) * HID + kt + lkA];
        As[lkA + 0][lmA] = a.x; As[lkA + 1][lmA] = a.y; As[lkA + 2][lmA] = a.z; As[lkA + 3][lmA] = a.w;
        float4 bv4 = *(const float4*)&Wfc[(size_t)(kt + lkB) * HID + n0 + lnB];
        *(float4*)&Bs[lkB][lnB] = bv4;
        __syncthreads();
        #pragma unroll
        for (int k = 0; k < 16; k++) {
            float a0 = As[k][ty * 4 + 0], a1 = As[k][ty * 4 + 1];
            float a2 = As[k][ty * 4 + 2], a3 = As[k][ty * 4 + 3];
            float4 bv = *(const float4*)&Bs[k][tx * 4];
            acc[0][0] += a0 * bv.x; acc[0][1] += a0 * bv.y; acc[0][2] += a0 * bv.z; acc[0][3] += a0 * bv.w;
            acc[1][0] += a1 * bv.x; acc[1][1] += a1 * bv.y; acc[1][2] += a1 * bv.z; acc[1][3] += a1 * bv.w;
            acc[2][0] += a2 * bv.x; acc[2][1] += a2 * bv.y; acc[2][2] += a2 * bv.z; acc[2][3] += a2 * bv.w;
            acc[3][0] += a3 * bv.x; acc[3][1] += a3 * bv.y; acc[3][2] += a3 * bv.z; acc[3][3] += a3 * bv.w;
        }
        __syncthreads();
    }
    #pragma unroll
    for (int i = 0; i < 4; i++) {
        int n = m0 + ty * 4 + i;
        int npr = 4 * (n & 1023) + (n >> 10);
        *(float4*)&d_Wt[(size_t)npr * KC + n0 + tx * 4] =
            make_float4(tf32r(acc[i][0]), tf32r(acc[i][1]), tf32r(acc[i][2]), tf32r(acc[i][3]));
    }
}

__global__ void prep_whh(const float* __restrict__ Whh) {
    int idx = blockIdx.x * blockDim.x + threadIdx.x;     // NG*HID/4
    int n = idx >> 8, k = (idx & 255) * 4;
    float4 v = *(const float4*)&Whh[(size_t)n * HID + k];
    int npr = 4 * (n & 1023) + (n >> 10);
    *(float4*)&d_Wt[(size_t)npr * KC + HID + k] =
        make_float4(tf32r(v.x), tf32r(v.y), tf32r(v.z), tf32r(v.w));
}

__global__ void prep_wfc(const float* __restrict__ Wfc) {
    int idx = blockIdx.x * blockDim.x + threadIdx.x;     // HID*HID/4
    float4 v = *(const float4*)&Wfc[(size_t)idx * 4];
    *(float4*)&d_Wf[(size_t)idx * 4] = make_float4(tf32r(v.x), tf32r(v.y), tf32r(v.z), tf32r(v.w));
}

__global__ void prep_bias(const float* __restrict__ Wih, const float* __restrict__ bih,
                          const float* __restrict__ bhh, const float* __restrict__ bfc) {
    int n = (blockIdx.x * blockDim.x + threadIdx.x) >> 5;
    int lane = threadIdx.x & 31;
    const float* row = Wih + (size_t)n * HID;
    float s = 0.f;
    for (int o = lane; o < HID; o += 32) s += row[o] * bfc[o];
    #pragma unroll
    for (int off = 16; off; off >>= 1) s += __shfl_xor_sync(0xFFFFFFFFu, s, off);
    if (lane == 0) {
        int npr = 4 * (n & 1023) + (n >> 10);
        float b0 = bih[n] + bhh[n];
        d_b0[npr] = b0;
        d_bF[npr] = b0 + s;
    }
}

__global__ void prep_A0(const float* __restrict__ cvec) {
    int idx = blockIdx.x * blockDim.x + threadIdx.x;     // NB*HID
    d_Ac0[idx] = 0.f;                    // i_0 = 0 -> c-part of step-0 A is zero
    d_Ah0[idx] = tf32r(cvec[idx]);       // h_{-1} = c_vector
}

// ================= host =================
extern "C" void kernel_launch(void* const* d_in, const int* in_sizes, int n_in,
                              void* d_out, int out_size) {
    (void)in_sizes; (void)n_in; (void)out_size;
    const float* c_vector = (const float*)d_in[0];
    const float* W_ih     = (const float*)d_in[1];
    const float* W_hh     = (const float*)d_in[2];
    const float* b_ih     = (const float*)d_in[3];
    const float* b_hh     = (const float*)d_in[4];
    const float* W_fc     = (const float*)d_in[5];
    const float* b_fc     = (const float*)d_in[6];
    float* out = (float*)d_out;

    float *pAc0, *pAc1, *pAh0, *pAh1, *pWt, *pWf, *pb0, *pbF;
    cudaGetSymbolAddress((void**)&pWt,  d_Wt);
    cudaGetSymbolAddress((void**)&pAc0, d_Ac0);
    cudaGetSymbolAddress((void**)&pAc1, d_Ac1);
    cudaGetSymbolAddress((void**)&pAh0, d_Ah0);
    cudaGetSymbolAddress((void**)&pAh1, d_Ah1);
    cudaGetSymbolAddress((void**)&pWf,  d_Wf);
    cudaGetSymbolAddress((void**)&pb0,  d_b0);
    cudaGetSymbolAddress((void**)&pbF,  d_bF);

    cudaFuncSetAttribute(gemm_k<0>, cudaFuncAttributeMaxDynamicSharedMemorySize, SMEM_BYTES);
    cudaFuncSetAttribute(gemm_k<1>, cudaFuncAttributeMaxDynamicSharedMemorySize, SMEM_BYTES);

    prep_wc  <<<dim3(HID / 64, NG / 64), 256>>>(W_ih, W_fc);
    prep_whh <<<(NG * HID / 4) / 256, 256>>>(W_hh);
    prep_wfc <<<(HID * HID / 4) / 256, 256>>>(W_fc);
    prep_bias<<<NG * 32 / 1024, 1024>>>(W_ih, b_ih, b_hh, b_fc);
    prep_A0  <<<(NB * HID) / 256, 256>>>(c_vector);

    for (int t = 0; t < TSTEPS; t++) {
        const float* Ac = (t & 1) ? pAc1 : pAc0;
        const float* Ah = (t & 1) ? pAh1 : pAh0;
        float* Acw = (t & 1) ? pAc0 : pAc1;
        float* Ahw = (t & 1) ? pAh0 : pAh1;
        const float* pb = (t == 0) ? pb0 : pbF;
        gemm_k<0><<<dim3(NG / BN, NB / BM, 2), 128, SMEM_BYTES>>>(
            Ac, Ah, (long long)HID, pWt, (long long)KC,
            pb, c_vector, out, (long long)NG, Acw, Ahw, t, 1024);
    }

    // outputs = c_states @ W_fc^T + b_fc (rows r = b*T + t match the output layout)
    gemm_k<1><<<dim3(HID / BN, (NB * TSTEPS) / BM, 1), 128, SMEM_BYTES>>>(
        out + SOFF, (const float*)0, (long long)HID, pWf, (long long)HID,
        b_fc, (const float*)0, out + 2 * SOFF, (long long)HID,
        (float*)0, (float*)0, 0, 1024);
}

// round 11
// speedup vs baseline: 2.0013x; 2.0013x over previous
#include <cuda_runtime.h>
#include <cuda_fp16.h>
#include <math.h>
#include <stdint.h>
#include <stddef.h>

#define TSTEPS 256
#define HID    1024
#define NB     256
#define KC     2048
#define NG     4096
#define SOFF   ((size_t)NB * TSTEPS * HID)

// ---------------- static device scratch ----------------
__device__ __align__(256) __half d_Wt[(size_t)NG * KC];   // reordered [n'=4d+g][k]; k<1024: W_c, k>=1024: W_hh (fp16)
__device__ __align__(256) __half d_Ac0[(size_t)NB * HID]; // c-part A ping-pong (fp16)
__device__ __align__(256) __half d_Ac1[(size_t)NB * HID];
__device__ __align__(256) __half d_Ah0[(size_t)NB * HID]; // h-part A ping-pong (fp16)
__device__ __align__(256) __half d_Ah1[(size_t)NB * HID];
__device__ __align__(256) __half d_Wf[(size_t)HID * HID]; // fp16 W_fc [o][h]
__device__ __align__(256) __half d_Ch[(size_t)NB * TSTEPS * HID]; // fp16 c_states for final GEMM
__device__ __align__(256) float  d_P[2 * 64 * 16384];     // split-K partials: [kz][tile][128*128]
__device__ float d_b0[NG];                                // reordered b_ih+b_hh          (t = 0)
__device__ float d_bF[NG];                                // reordered + W_ih@b_fc folded (t >= 1)

__device__ __forceinline__ float sigf(float x) { return 1.0f / (1.0f + expf(-x)); }
__device__ __forceinline__ uint32_t smem_u32(const void* p) {
    uint32_t a;
    asm("{ .reg .u64 t; cvta.to.shared.u64 t, %1; cvt.u32.u64 %0, t; }" : "=r"(a) : "l"(p));
    return a;
}

#define CPA(dst, src) asm volatile("cp.async.cg.shared.global [%0], [%1], 16;" :: "r"(dst), "l"(src))
#define CPC()         asm volatile("cp.async.commit_group;" ::: "memory")
#define CPW(n)        asm volatile("cp.async.wait_group %0;" :: "n"(n) : "memory")

#define MMA16(d, a, b) asm volatile( \
    "mma.sync.aligned.m16n8k16.row.col.f32.f16.f16.f32 " \
    "{%0,%1,%2,%3}, {%4,%5,%6,%7}, {%8,%9}, {%0,%1,%2,%3};" \
    : "+f"((d)[0]), "+f"((d)[1]), "+f"((d)[2]), "+f"((d)[3]) \
    : "r"((a)[0]), "r"((a)[1]), "r"((a)[2]), "r"((a)[3]), "r"((b)[0]), "r"((b)[1]))

// ---------------- GEMM tiling: CTA 128x128, 4 warps (warp tile 64x64), BK=32 halfs, 3 stages ----------------
#define BM     128
#define BN     128
#define BK     32
#define STAGES 3
#define HSTR   40                         // halfs per smem row (pad 8 -> conflict-free)
#define A_BYTES (BM * HSTR * 2)           // 10240 B
#define STG_B   (2 * A_BYTES)             // 20480 B per stage (A + B)
#define SMEM_BYTES 65536                  // stages 61440 B; Cs (fp32 128x128 = 64KB) reuses

// ================= fp16 mma.sync GEMM =================
// MODE 0: split-K gates GEMM -> raw fp32 partials (pout = d_P base; blockIdx.z picks K-half)
// MODE 1: plain GEMM + bias (final outputs)
template<int MODE>
__global__ void __launch_bounds__(128) gemm_k(
    const __half* __restrict__ Ac, const __half* __restrict__ Ah, long long lda,
    const __half* __restrict__ Bg, long long ldb,
    const float* __restrict__ pb,
    float* __restrict__ pout, long long ldo, int ktot)
{
    extern __shared__ __align__(16) char smraw[];
    const int tid = threadIdx.x;
    const int n0 = blockIdx.x * BN;
    const int m0 = blockIdx.y * BM;
    const int kz = blockIdx.z;
    const int w = tid >> 5, lane = tid & 31;
    const int wm = w & 1, wn = w >> 1;          // 2 x 2 warp grid, warp tile 64x64
    const int gid = lane >> 2, tig = lane & 3;

    const __half* Ag = (MODE == 0) ? (kz ? Ah : Ac) : Ac;
    const __half* Bb = Bg + ((MODE == 0) ? kz * 1024 : 0);
    float* po = pout + ((MODE == 0)
        ? ((size_t)kz * 64 + (size_t)(blockIdx.y * gridDim.x + blockIdx.x)) * 16384 : 0);

    const __half* Atile = Ag + (size_t)m0 * lda;
    const __half* Btile = Bb + (size_t)n0 * ldb;
    const uint32_t sbase = smem_u32(smraw);

    float acc[4][8][4];
    #pragma unroll
    for (int i = 0; i < 4; i++)
        #pragma unroll
        for (int j = 0; j < 8; j++)
            #pragma unroll
            for (int q = 0; q < 4; q++) acc[i][j][q] = 0.f;

    const int KT = ktot / BK;

    auto load_stage = [&](int stage, int kt) {
        uint32_t sa = sbase + (uint32_t)(stage * STG_B);
        uint32_t sb = sa + (uint32_t)A_BYTES;
        #pragma unroll
        for (int i = 0; i < 4; i++) {
            int idx = tid + i * 128;            // 0..511: 128 rows x 4 16B-chunks
            int r = idx >> 2, ch = idx & 3;
            CPA(sa + (uint32_t)(r * (HSTR * 2) + ch * 16), Atile + (size_t)r * lda + kt + ch * 8);
        }
        #pragma unroll
        for (int i = 0; i < 4; i++) {
            int idx = tid + i * 128;
            int r = idx >> 2, ch = idx & 3;
            CPA(sb + (uint32_t)(r * (HSTR * 2) + ch * 16), Btile + (size_t)r * ldb + kt + ch * 8);
        }
        CPC();
    };

    load_stage(0, 0);
    load_stage(1, BK);

    for (int kt = 0; kt < KT; kt++) {
        CPW(STAGES - 2);
        __syncthreads();
        int kn = kt + STAGES - 1;
        if (kn < KT) load_stage(kn % STAGES, kn * BK); else CPC();

        const uint32_t* wA = (const uint32_t*)(smraw + (size_t)(kt % STAGES) * STG_B);
        const uint32_t* wB = (const uint32_t*)(smraw + (size_t)(kt % STAGES) * STG_B + A_BYTES);
        #pragma unroll
        for (int ks = 0; ks < 2; ks++) {        // two k16 steps per BK=32
            int kw = ks * 8;                    // word offset (16 halfs = 8 words)
            uint32_t a[4][4], b[8][2];
            #pragma unroll
            for (int mt = 0; mt < 4; mt++) {
                int mr = wm * 64 + mt * 16 + gid;
                a[mt][0] = wA[(mr)     * (HSTR / 2) + kw + tig];
                a[mt][1] = wA[(mr + 8) * (HSTR / 2) + kw + tig];
                a[mt][2] = wA[(mr)     * (HSTR / 2) + kw + tig + 4];
                a[mt][3] = wA[(mr + 8) * (HSTR / 2) + kw + tig + 4];
            }
            #pragma unroll
            for (int nt = 0; nt < 8; nt++) {
                int nc = wn * 64 + nt * 8 + gid;
                b[nt][0] = wB[nc * (HSTR / 2) + kw + tig];
                b[nt][1] = wB[nc * (HSTR / 2) + kw + tig + 4];
            }
            #pragma unroll
            for (int mt = 0; mt < 4; mt++)
                #pragma unroll
                for (int nt = 0; nt < 8; nt++)
                    MMA16(acc[mt][nt], a[mt], b[nt]);
        }
        __syncthreads();
    }

    // ---- stash C tile to smem, then coalesced float4 stores ----
    float* Cs = (float*)smraw;
    #pragma unroll
    for (int mt = 0; mt < 4; mt++) {
        int row = wm * 64 + mt * 16 + gid;
        #pragma unroll
        for (int nt = 0; nt < 8; nt++) {
            int col = wn * 64 + nt * 8 + 2 * tig;
            *(float2*)&Cs[(row)     * BN + col] = make_float2(acc[mt][nt][0], acc[mt][nt][1]);
            *(float2*)&Cs[(row + 8) * BN + col] = make_float2(acc[mt][nt][2], acc[mt][nt][3]);
        }
    }
    __syncthreads();

    #pragma unroll
    for (int i = 0; i < 32; i++) {
        int e = tid + i * 128;                  // 0..4095 float4 slots
        int r = e >> 5, c4 = (e & 31) * 4;
        float4 v = *(float4*)&Cs[r * BN + c4];
        if (MODE == 1) {
            float4 bz = *(const float4*)&pb[n0 + c4];
            v = make_float4(v.x + bz.x, v.y + bz.y, v.z + bz.z, v.w + bz.w);
            *(float4*)&pout[(size_t)(m0 + r) * ldo + n0 + c4] = v;
        } else {
            *(float4*)&po[4 * e] = v;           // linear partial tile
        }
    }
}

// ================= combine + LSTM cell =================
__global__ void __launch_bounds__(256) cell_k(
    const float* __restrict__ cvec, const float* __restrict__ pb,
    float* __restrict__ pout, __half* __restrict__ pAc, __half* __restrict__ pAh, int t)
{
    int e = blockIdx.x * blockDim.x + threadIdx.x;  // 0 .. NB*HID
    int b = e >> 10, d = e & 1023;
    // partial tile id: by = b>>7 (of 2), bx = d>>5 (of 32); tile = by*32 + bx
    int tile = (b >> 7) * 32 + (d >> 5);
    int loc  = (b & 127) * 128 + (d & 31) * 4;       // row-in-tile * BN + col
    const float* s0 = d_P + (size_t)tile * 16384 + loc;
    const float* s1 = d_P + (size_t)(64 + tile) * 16384 + loc;
    float4 g0 = *(const float4*)s0;
    float4 g1 = *(const float4*)s1;
    float4 bz = *(const float4*)&pb[4 * d];
    float ig = g0.x + g1.x + bz.x;
    float fg = g0.y + g1.y + bz.y;
    float gg = g0.z + g1.z + bz.z;
    float og = g0.w + g1.w + bz.w;
    float cp = (t == 0) ? cvec[e]
                        : pout[SOFF + (size_t)b * (TSTEPS * HID) + (size_t)(t - 1) * HID + d];
    float cn = sigf(fg) * cp + sigf(ig) * tanhf(gg);
    float hn = sigf(og) * tanhf(cn);
    size_t ro = (size_t)b * (TSTEPS * HID) + (size_t)t * HID + d;
    pout[ro]        = hn;
    pout[SOFF + ro] = cn;
    pAc[e] = __float2half_rn(cn);
    pAh[e] = __float2half_rn(hn);
    d_Ch[ro] = __float2half_rn(cn);              // row r = b*T + t for the final GEMM
}

// ================= prep kernels =================
// W_c = W_ih @ W_fc (exact fp32 SIMT), stored reordered + fp16-rounded into d_Wt[:, 0:1024]
__global__ void prep_wc(const float* __restrict__ Wih, const float* __restrict__ Wfc) {
    __shared__ float As[16][65];
    __shared__ float Bs[16][64];
    int n0 = blockIdx.x * 64;          // output k (0..1023)
    int m0 = blockIdx.y * 64;          // row of W_ih (gate-major n, 0..4095)
    int tid = threadIdx.x;
    int tx = tid & 15, ty = tid >> 4;
    int lmA = tid >> 2, lkA = (tid & 3) * 4;
    int lkB = tid >> 4, lnB = (tid & 15) * 4;
    float acc[4][4] = {};
    for (int kt = 0; kt < HID; kt += 16) {
        float4 a = *(const float4*)&Wih[(size_t)(m0 + lmA) * HID + kt + lkA];
        As[lkA + 0][lmA] = a.x; As[lkA + 1][lmA] = a.y; As[lkA + 2][lmA] = a.z; As[lkA + 3][lmA] = a.w;
        float4 bv4 = *(const float4*)&Wfc[(size_t)(kt + lkB) * HID + n0 + lnB];
        *(float4*)&Bs[lkB][lnB] = bv4;
        __syncthreads();
        #pragma unroll
        for (int k = 0; k < 16; k++) {
            float a0 = As[k][ty * 4 + 0], a1 = As[k][ty * 4 + 1];
            float a2 = As[k][ty * 4 + 2], a3 = As[k][ty * 4 + 3];
            float4 bv = *(const float4*)&Bs[k][tx * 4];
            acc[0][0] += a0 * bv.x; acc[0][1] += a0 * bv.y; acc[0][2] += a0 * bv.z; acc[0][3] += a0 * bv.w;
            acc[1][0] += a1 * bv.x; acc[1][1] += a1 * bv.y; acc[1][2] += a1 * bv.z; acc[1][3] += a1 * bv.w;
            acc[2][0] += a2 * bv.x; acc[2][1] += a2 * bv.y; acc[2][2] += a2 * bv.z; acc[2][3] += a2 * bv.w;
            acc[3][0] += a3 * bv.x; acc[3][1] += a3 * bv.y; acc[3][2] += a3 * bv.z; acc[3][3] += a3 * bv.w;
        }
        __syncthreads();
    }
    #pragma unroll
    for (int i = 0; i < 4; i++) {
        int n = m0 + ty * 4 + i;
        int npr = 4 * (n & 1023) + (n >> 10);
        __half* dst = &d_Wt[(size_t)npr * KC + n0 + tx * 4];
        dst[0] = __float2half_rn(acc[i][0]); dst[1] = __float2half_rn(acc[i][1]);
        dst[2] = __float2half_rn(acc[i][2]); dst[3] = __float2half_rn(acc[i][3]);
    }
}

__global__ void prep_whh(const float* __restrict__ Whh) {
    int idx = blockIdx.x * blockDim.x + threadIdx.x;     // NG*HID/4
    int n = idx >> 8, k = (idx & 255) * 4;
    float4 v = *(const float4*)&Whh[(size_t)n * HID + k];
    int npr = 4 * (n & 1023) + (n >> 10);
    __half* dst = &d_Wt[(size_t)npr * KC + HID + k];
    dst[0] = __float2half_rn(v.x); dst[1] = __float2half_rn(v.y);
    dst[2] = __float2half_rn(v.z); dst[3] = __float2half_rn(v.w);
}

__global__ void prep_wfc(const float* __restrict__ Wfc) {
    int idx = blockIdx.x * blockDim.x + threadIdx.x;     // HID*HID/4
    float4 v = *(const float4*)&Wfc[(size_t)idx * 4];
    __half* dst = &d_Wf[(size_t)idx * 4];
    dst[0] = __float2half_rn(v.x); dst[1] = __float2half_rn(v.y);
    dst[2] = __float2half_rn(v.z); dst[3] = __float2half_rn(v.w);
}

__global__ void prep_bias(const float* __restrict__ Wih, const float* __restrict__ bih,
                          const float* __restrict__ bhh, const float* __restrict__ bfc) {
    int n = (blockIdx.x * blockDim.x + threadIdx.x) >> 5;
    int lane = threadIdx.x & 31;
    const float* row = Wih + (size_t)n * HID;
    float s = 0.f;
    for (int o = lane; o < HID; o += 32) s += row[o] * bfc[o];
    #pragma unroll
    for (int off = 16; off; off >>= 1) s += __shfl_xor_sync(0xFFFFFFFFu, s, off);
    if (lane == 0) {
        int npr = 4 * (n & 1023) + (n >> 10);
        float b0 = bih[n] + bhh[n];
        d_b0[npr] = b0;
        d_bF[npr] = b0 + s;
    }
}

__global__ void prep_A0(const float* __restrict__ cvec) {
    int idx = blockIdx.x * blockDim.x + threadIdx.x;     // NB*HID
    d_Ac0[idx] = __float2half_rn(0.f);   // i_0 = 0 -> c-part of step-0 A is zero
    d_Ah0[idx] = __float2half_rn(cvec[idx]);  // h_{-1} = c_vector
}

// ================= host =================
extern "C" void kernel_launch(void* const* d_in, const int* in_sizes, int n_in,
                              void* d_out, int out_size) {
    (void)in_sizes; (void)n_in; (void)out_size;
    const float* c_vector = (const float*)d_in[0];
    const float* W_ih     = (const float*)d_in[1];
    const float* W_hh     = (const float*)d_in[2];
    const float* b_ih     = (const float*)d_in[3];
    const float* b_hh     = (const float*)d_in[4];
    const float* W_fc     = (const float*)d_in[5];
    const float* b_fc     = (const float*)d_in[6];
    float* out = (float*)d_out;

    __half *pWt, *pAc0, *pAc1, *pAh0, *pAh1, *pWf, *pCh;
    float *pb0, *pbF, *pP;
    cudaGetSymbolAddress((void**)&pWt,  d_Wt);
    cudaGetSymbolAddress((void**)&pAc0, d_Ac0);
    cudaGetSymbolAddress((void**)&pAc1, d_Ac1);
    cudaGetSymbolAddress((void**)&pAh0, d_Ah0);
    cudaGetSymbolAddress((void**)&pAh1, d_Ah1);
    cudaGetSymbolAddress((void**)&pWf,  d_Wf);
    cudaGetSymbolAddress((void**)&pCh,  d_Ch);
    cudaGetSymbolAddress((void**)&pP,   d_P);
    cudaGetSymbolAddress((void**)&pb0,  d_b0);
    cudaGetSymbolAddress((void**)&pbF,  d_bF);

    cudaFuncSetAttribute(gemm_k<0>, cudaFuncAttributeMaxDynamicSharedMemorySize, SMEM_BYTES);
    cudaFuncSetAttribute(gemm_k<1>, cudaFuncAttributeMaxDynamicSharedMemorySize, SMEM_BYTES);

    prep_wc  <<<dim3(HID / 64, NG / 64), 256>>>(W_ih, W_fc);
    prep_whh <<<(NG * HID / 4) / 256, 256>>>(W_hh);
    prep_wfc <<<(HID * HID / 4) / 256, 256>>>(W_fc);
    prep_bias<<<NG * 32 / 1024, 1024>>>(W_ih, b_ih, b_hh, b_fc);
    prep_A0  <<<(NB * HID) / 256, 256>>>(c_vector);

    for (int t = 0; t < TSTEPS; t++) {
        const __half* Ac = (t & 1) ? pAc1 : pAc0;
        const __half* Ah = (t & 1) ? pAh1 : pAh0;
        __half* Acw = (t & 1) ? pAc0 : pAc1;
        __half* Ahw = (t & 1) ? pAh0 : pAh1;
        const float* pb = (t == 0) ? pb0 : pbF;
        gemm_k<0><<<dim3(NG / BN, NB / BM, 2), 128, SMEM_BYTES>>>(
            Ac, Ah, (long long)HID, pWt, (long long)KC,
            (const float*)0, pP, 0, 1024);
        cell_k<<<(NB * HID) / 256, 256>>>(c_vector, pb, out, Acw, Ahw, t);
    }

    // outputs = c_states @ W_fc^T + b_fc (rows r = b*T + t match the output layout)
    gemm_k<1><<<dim3(HID / BN, (NB * TSTEPS) / BM, 1), 128, SMEM_BYTES>>>(
        pCh, (const __half*)0, (long long)HID, pWf, (long long)HID,
        b_fc, out + 2 * SOFF, (long long)HID, 1024);
}